// round 3
// baseline (speedup 1.0000x reference)
#include <cuda_runtime.h>
#include <cuda_bf16.h>
#include <cstdint>

// Problem constants
#define TSTEPS 512
#define BB 64
#define II 128
#define HH 512
#define OO 128
#define KK 32
#define ZK 640                  // I + H
#define NBLK 139                // 128 gate blocks + 11 out blocks
#define NTH 256
#define GT (NBLK*NTH)

#define ZSM_FLOATS (ZK*BB)          // 40960 floats = 163840 B
#define ZSM_BYTES  (ZSM_FLOATS*4)
#define WSM_BYTES  (ZK*12*8)        // 61440 B : [k][12] f32x2-dup
#define WD_BYTES   (4*KK*4)         // 512 B
#define SMEM_BYTES (ZSM_BYTES + WSM_BYTES + WD_BYTES)   // 225792

typedef unsigned long long ull;

// ------------- static device scratch (no allocations) -------------
__device__ float g_xT[TSTEPS*II*BB];     // inputs transposed: [t][k][b]
__device__ float g_zH[HH*BB];            // h_{t-1}: [h][b]
__device__ float g_ring[KK*HH*BB];       // cell-state ring: [slot][h][b]
__device__ unsigned g_cnt;
__device__ volatile unsigned g_sense_v;

// ------------- helpers -------------
__device__ __forceinline__ ull ffma2(ull a, ull b, ull c) {
    ull d;
    asm("fma.rn.f32x2 %0, %1, %2, %3;" : "=l"(d) : "l"(a), "l"(b), "l"(c));
    return d;
}
__device__ __forceinline__ ull dup2(float w) {
    unsigned u = __float_as_uint(w);
    return ((ull)u << 32) | (ull)u;
}
__device__ __forceinline__ float lo32(ull v) { return __uint_as_float((unsigned)v); }
__device__ __forceinline__ float hi32(ull v) { return __uint_as_float((unsigned)(v >> 32)); }
__device__ __forceinline__ float sigm(float x) { return 1.f / (1.f + __expf(-x)); }

// Sense-reversing grid barrier; g_cnt/g_sense_v self-restore (even total calls).
__device__ __forceinline__ void gridbar(unsigned n) {
    __threadfence();               // order this thread's global stores first
    __syncthreads();
    if (threadIdx.x == 0) {
        unsigned s = (~n) & 1u;
        if (atomicAdd(&g_cnt, 1u) == NBLK - 1) {
            g_cnt = 0;
            __threadfence();
            g_sense_v = s;
        } else {
            while (g_sense_v != s) __nanosleep(32);
        }
    }
    __syncthreads();
}

extern __shared__ char smem_raw[];

__global__ void __launch_bounds__(NTH, 1)
mlstm_kernel(const float* __restrict__ inputs,
             const float* __restrict__ W_i, const float* __restrict__ b_i,
             const float* __restrict__ W_o, const float* __restrict__ b_o,
             const float* __restrict__ W_c, const float* __restrict__ b_c,
             const float* __restrict__ W_out, const float* __restrict__ b_out,
             const float* __restrict__ d_values,
             float* __restrict__ out)
{
    float* zsm   = (float*)smem_raw;                         // [640][64]
    ull*   wsm   = (ull*)(smem_raw + ZSM_BYTES);             // [640][12]
    float* wd_sm = (float*)(smem_raw + ZSM_BYTES + WSM_BYTES); // [4][32]
    ull*   redsm = (ull*)smem_raw;                           // reuse: [8][12][32]
    float* pre_sm = (float*)(smem_raw + 8*12*32*8);          // reuse: [12][64]

    const int tid  = threadIdx.x;
    const int blk  = blockIdx.x;
    const int gtid = blk * NTH + tid;
    const int lane = tid & 31;
    const int wid  = tid >> 5;

    const bool isOut = (blk >= 128);
    const int h0    = blk * 4;                 // gate blocks: 4 h each
    const int oc0   = (blk - 128) * 12;        // out blocks
    const int ncols = isOut ? ((128 - oc0) < 12 ? (128 - oc0) : 12) : 12;

    unsigned barid = 0;

    // ---------------- init ----------------
    // Weights -> smem, duplicated for f32x2. Gate block col j = hh*3 + g.
    // Out block col j = output column oc0+j, zero-padded for k<II and j>=ncols.
    for (int idx = tid; idx < ZK * 12; idx += NTH) {
        int k = idx / 12;
        int j = idx - k * 12;
        float w = 0.f;
        if (!isOut) {
            int hh = j / 3, g = j - hh * 3;
            const float* W = (g == 0) ? W_i : (g == 1) ? W_o : W_c;
            w = W[k * HH + h0 + hh];
        } else if (j < ncols && k >= II) {
            w = W_out[(k - II) * OO + oc0 + j];
        }
        wsm[idx] = dup2(w);
    }
    // Frac-diff weights for this block's 4 h (gate blocks): wd_sm[hh][j] = v_{K-j}
    float rbi = 0.f, rbo = 0.f, rbc = 0.f;
    const int eh = tid >> 6;      // elementwise hh (0..3)
    const int eb = tid & 63;      // elementwise b
    if (!isOut) {
        if (tid < 4) {
            float dv = 0.5f * sigm(d_values[h0 + tid]);
            float v = 1.f;
            for (int i = 0; i < KK; ++i) {
                v = v * ((float)i - dv) / ((float)i + 1.f);
                wd_sm[tid * KK + (KK - 1 - i)] = v;
            }
        }
        rbi = b_i[h0 + eh]; rbo = b_o[h0 + eh]; rbc = b_c[h0 + eh];
    }
    // Transpose inputs once: g_xT[t][k][b]  (reads coalesced over k)
    for (int idx = gtid; idx < TSTEPS * II * BB; idx += GT) {
        int t = idx >> 13;
        int r = idx & 8191;
        int k = r & 127, b = r >> 7;
        g_xT[(size_t)t * 8192 + k * 64 + b] = inputs[((size_t)t * BB + b) * II + k];
    }
    // Zero h and ring
    for (int idx = gtid; idx < HH * BB; idx += GT) g_zH[idx] = 0.f;
    for (int idx = gtid; idx < KK * HH * BB; idx += GT) g_ring[idx] = 0.f;
    __syncthreads();
    gridbar(barid++);

    // ---------------- main scan ----------------
    // Iter u: stage z=[x_u ; h_{u-1}] -> gate GEMM+elementwise (u<512),
    //         out GEMM for step u-1 (u>=1). ONE grid barrier per iter.
    for (int u = 0; u <= TSTEPS; ++u) {
        // Stage x rows (k<128). At u==512 leave stale (out weights are 0 there).
        if (u < TSTEPS) {
            for (int it = tid; it < II * 16; it += NTH) {
                int k = it >> 4, q = it & 15;
                *(float4*)&zsm[k * 64 + q * 4] =
                    __ldcg((const float4*)&g_xT[(size_t)u * 8192 + k * 64 + q * 4]);
            }
        }
        // Stage h rows (always; zeros at u=0 from init)
        for (int it = tid; it < HH * 16; it += NTH) {
            int k = it >> 4, q = it & 15;
            *(float4*)&zsm[(II + k) * 64 + q * 4] =
                __ldcg((const float4*)&g_zH[k * 64 + q * 4]);
        }
        __syncthreads();

        const bool active = isOut ? (u >= 1) : (u < TSTEPS);
        ull acc[12];
        if (active) {
            // warp wid covers k in [wid*80, wid*80+80)
            const float* zp = zsm + wid * 80 * 64 + lane * 2;
            const ulonglong2* wp = (const ulonglong2*)(wsm + (size_t)wid * 80 * 12);
            #pragma unroll
            for (int j = 0; j < 12; ++j) acc[j] = 0ULL;
            #pragma unroll 4
            for (int kk = 0; kk < 80; ++kk) {
                ull z = *(const ull*)(zp + kk * 64);
                ulonglong2 w0 = wp[kk * 6 + 0];
                ulonglong2 w1 = wp[kk * 6 + 1];
                ulonglong2 w2 = wp[kk * 6 + 2];
                acc[0] = ffma2(z, w0.x, acc[0]);  acc[1] = ffma2(z, w0.y, acc[1]);
                acc[2] = ffma2(z, w1.x, acc[2]);  acc[3] = ffma2(z, w1.y, acc[3]);
                acc[4] = ffma2(z, w2.x, acc[4]);  acc[5] = ffma2(z, w2.y, acc[5]);
                ulonglong2 w3 = wp[kk * 6 + 3];
                ulonglong2 w4 = wp[kk * 6 + 4];
                ulonglong2 w5 = wp[kk * 6 + 5];
                acc[6] = ffma2(z, w3.x, acc[6]);  acc[7]  = ffma2(z, w3.y, acc[7]);
                acc[8] = ffma2(z, w4.x, acc[8]);  acc[9]  = ffma2(z, w4.y, acc[9]);
                acc[10] = ffma2(z, w5.x, acc[10]); acc[11] = ffma2(z, w5.y, acc[11]);
            }
        }
        __syncthreads();   // all warps done reading zsm before redsm overwrite
        if (active) {
            #pragma unroll
            for (int j = 0; j < 12; ++j)
                redsm[(wid * 12 + j) * 32 + lane] = acc[j];
        }
        __syncthreads();
        if (active) {
            // reduce 8 k-partials -> pre_sm[12][64]
            for (int item = tid; item < 12 * 32; item += NTH) {
                int j = item >> 5, bp = item & 31;
                float slo = 0.f, shi = 0.f;
                #pragma unroll
                for (int w = 0; w < 8; ++w) {
                    ull v = redsm[((w * 12) + j) * 32 + bp];
                    slo += lo32(v); shi += hi32(v);
                }
                pre_sm[j * 64 + 2 * bp]     = slo;
                pre_sm[j * 64 + 2 * bp + 1] = shi;
            }
        }
        __syncthreads();
        if (active) {
            if (isOut) {
                // outputs for step u-1
                for (int item = tid; item < ncols * 64; item += NTH) {
                    int j = item >> 6, b = item & 63;
                    int oc = oc0 + j;
                    out[((size_t)(u - 1) * BB + b) * OO + oc] = pre_sm[j * 64 + b] + b_out[oc];
                }
            } else {
                // elementwise update for (h0+eh, eb)
                float pi = pre_sm[(eh * 3 + 0) * 64 + eb] + rbi;
                float po = pre_sm[(eh * 3 + 1) * 64 + eb] + rbo;
                float pc = pre_sm[(eh * 3 + 2) * 64 + eb] + rbc;
                float iv = sigm(pi);
                float ov = sigm(po);
                float gv = tanhf(pc);
                int h = h0 + eh;
                // lag = sum_j wd[j]*c_{u-K+j}; slot of c_{u-K+j} = (u+j)&31
                float l0 = 0.f, l1 = 0.f, l2 = 0.f, l3 = 0.f;
                #pragma unroll
                for (int j = 0; j < KK; j += 4) {
                    int s0 = (u + j    ) & 31;
                    int s1 = (u + j + 1) & 31;
                    int s2 = (u + j + 2) & 31;
                    int s3 = (u + j + 3) & 31;
                    l0 += wd_sm[eh * KK + j    ] * g_ring[(s0 << 15) + h * 64 + eb];
                    l1 += wd_sm[eh * KK + j + 1] * g_ring[(s1 << 15) + h * 64 + eb];
                    l2 += wd_sm[eh * KK + j + 2] * g_ring[(s2 << 15) + h * 64 + eb];
                    l3 += wd_sm[eh * KK + j + 3] * g_ring[(s3 << 15) + h * 64 + eb];
                }
                float cc = iv * gv - ((l0 + l1) + (l2 + l3));
                float hn = ov * tanhf(cc);
                g_ring[((u & 31) << 15) + h * 64 + eb] = cc;
                g_zH[h * 64 + eb] = hn;
                if (u == TSTEPS - 1)
                    out[(size_t)TSTEPS * BB * OO + (size_t)eb * HH + h] = hn;  // h_last[b][h]
            }
        }
        gridbar(barid++);
    }

    // hc_last[j][b][h]: slot j holds c_{480+j} (480 % 32 == 0)
    const size_t OFF_HC = (size_t)TSTEPS * BB * OO + (size_t)BB * HH;
    for (int idx = gtid; idx < KK * BB * HH; idx += GT) {
        int j = idx >> 15;
        int r = idx & 32767;
        int b = r >> 9, h = r & 511;
        out[OFF_HC + idx] = __ldcg(&g_ring[((size_t)j << 15) + h * 64 + b]);
    }
}

extern "C" void kernel_launch(void* const* d_in, const int* in_sizes, int n_in,
                              void* d_out, int out_size) {
    (void)in_sizes; (void)n_in; (void)out_size;
    const float* inputs   = (const float*)d_in[0];
    const float* W_i      = (const float*)d_in[1];
    const float* b_i      = (const float*)d_in[2];
    const float* W_o      = (const float*)d_in[3];
    const float* b_o      = (const float*)d_in[4];
    const float* W_c      = (const float*)d_in[5];
    const float* b_c      = (const float*)d_in[6];
    const float* W_out    = (const float*)d_in[7];
    const float* b_out    = (const float*)d_in[8];
    const float* d_values = (const float*)d_in[9];
    float* out = (float*)d_out;

    cudaFuncSetAttribute(mlstm_kernel, cudaFuncAttributeMaxDynamicSharedMemorySize, SMEM_BYTES);
    mlstm_kernel<<<NBLK, NTH, SMEM_BYTES>>>(inputs, W_i, b_i, W_o, b_o, W_c, b_c,
                                            W_out, b_out, d_values, out);
}

// round 4
// speedup vs baseline: 1.4413x; 1.4413x over previous
#include <cuda_runtime.h>
#include <cuda_bf16.h>
#include <cstdint>

// Problem constants
#define TSTEPS 512
#define BB 64
#define II 128
#define HH 512
#define OO 128
#define KK 32
#define ZK 640                  // I + H
#define NBLK 139                // 128 gate blocks + 11 out blocks
#define NTH 256
#define GT (NBLK*NTH)

// smem layout (bytes)
#define HSM_OFF   0             // h slice [512][64] f32 = 131072
#define XSM_OFF   131072        // x slice [128][64] f32 = 32768
#define WSM_OFF   163840        // weights [640][12] f32x2-dup = 61440
#define WD_OFF    225280        // frac-diff weights [4][32] f32 = 512
#define MBAR_OFF  225792        // 4 h mbars + 1 x mbar (8B each)
#define SMEM_BYTES (MBAR_OFF + 64)

typedef unsigned long long ull;

// ------------- static device scratch (no allocations) -------------
__device__ float g_xT[TSTEPS*II*BB];     // inputs transposed: [t][k][b]
__device__ float g_zH[HH*BB];            // h_{t-1}: [h][b]
__device__ float g_ring[KK*HH*BB];       // cell-state ring: [slot][h][b]
__device__ unsigned g_cnt;
__device__ volatile unsigned g_sense_v;

// ------------- helpers -------------
__device__ __forceinline__ ull ffma2(ull a, ull b, ull c) {
    ull d;
    asm("fma.rn.f32x2 %0, %1, %2, %3;" : "=l"(d) : "l"(a), "l"(b), "l"(c));
    return d;
}
__device__ __forceinline__ ull dup2(float w) {
    unsigned u = __float_as_uint(w);
    return ((ull)u << 32) | (ull)u;
}
__device__ __forceinline__ float sigm(float x) { return 1.f / (1.f + __expf(-x)); }

__device__ __forceinline__ unsigned smem_u32(const void* p) {
    return (unsigned)__cvta_generic_to_shared(p);
}
__device__ __forceinline__ void mbar_init(unsigned mbar, unsigned cnt) {
    asm volatile("mbarrier.init.shared.b64 [%0], %1;" :: "r"(mbar), "r"(cnt) : "memory");
}
__device__ __forceinline__ void mbar_expect(unsigned mbar, unsigned bytes) {
    asm volatile("mbarrier.arrive.expect_tx.shared.b64 _, [%0], %1;"
                 :: "r"(mbar), "r"(bytes) : "memory");
}
__device__ __forceinline__ void bulk_g2s(unsigned dst, const void* src,
                                         unsigned bytes, unsigned mbar) {
    asm volatile("cp.async.bulk.shared::cluster.global.mbarrier::complete_tx::bytes "
                 "[%0], [%1], %2, [%3];"
                 :: "r"(dst), "l"(src), "r"(bytes), "r"(mbar) : "memory");
}
__device__ __forceinline__ void mbar_wait(unsigned mbar, unsigned parity) {
    asm volatile(
        "{\n\t"
        ".reg .pred P;\n\t"
        "WAIT_%=:\n\t"
        "mbarrier.try_wait.parity.acquire.cta.shared::cta.b64 P, [%0], %1, 0x989680;\n\t"
        "@P bra.uni DONE_%=;\n\t"
        "bra.uni WAIT_%=;\n\t"
        "DONE_%=:\n\t"
        "}" :: "r"(mbar), "r"(parity) : "memory");
}

// Sense-reversing grid barrier; g_cnt/g_sense_v self-restore (even total calls).
__device__ __forceinline__ void gridbar(unsigned n) {
    __threadfence();
    __syncthreads();
    if (threadIdx.x == 0) {
        unsigned s = (~n) & 1u;
        if (atomicAdd(&g_cnt, 1u) == NBLK - 1) {
            g_cnt = 0;
            __threadfence();
            g_sense_v = s;
        } else {
            while (g_sense_v != s) __nanosleep(16);
        }
    }
    __syncthreads();
}

extern __shared__ char smem_raw[];

__global__ void __launch_bounds__(NTH, 1)
mlstm_kernel(const float* __restrict__ inputs,
             const float* __restrict__ W_i, const float* __restrict__ b_i,
             const float* __restrict__ W_o, const float* __restrict__ b_o,
             const float* __restrict__ W_c, const float* __restrict__ b_c,
             const float* __restrict__ W_out, const float* __restrict__ b_out,
             const float* __restrict__ d_values,
             float* __restrict__ out)
{
    float* hsm   = (float*)(smem_raw + HSM_OFF);    // [512][64]
    float* xsm   = (float*)(smem_raw + XSM_OFF);    // [128][64]
    ull*   wsm   = (ull*)(smem_raw + WSM_OFF);      // [640][12] permuted k
    float* wd_sm = (float*)(smem_raw + WD_OFF);     // [4][32]
    ull*   redsm = (ull*)(smem_raw + HSM_OFF);      // reuse h region: [8][12][32]
    float* redf  = (float*)redsm;

    const unsigned hbar0 = smem_u32(smem_raw + MBAR_OFF);  // 4 mbars, 8B apart
    const unsigned xbar  = hbar0 + 32;

    const int tid  = threadIdx.x;
    const int blk  = blockIdx.x;
    const int gtid = blk * NTH + tid;
    const int lane = tid & 31;
    const int wid  = tid >> 5;

    const bool isOut = (blk >= 128);
    const int h0  = blk * 4;                 // gate blocks: 4 h each
    const int oc0 = (blk - 128) * 12;        // out blocks
    const int eh  = tid >> 6;                // elementwise hh (0..3)
    const int eb  = tid & 63;                // elementwise b

    // ---------------- init ----------------
    if (tid == 0) {
        for (int c = 0; c < 4; ++c) mbar_init(hbar0 + c * 8, 1);
        mbar_init(xbar, 1);
    }
    // Weights -> smem, k-permuted: storage kp for warp w: [w*80, w*80+64) are
    // h-rows 128+w*64+i ; [w*80+64, w*80+80) are x-rows w*16+i.
    for (int idx = tid; idx < ZK * 12; idx += NTH) {
        int kp = idx / 12;
        int j  = idx - kp * 12;
        int w  = kp / 80, r = kp - w * 80;
        int k  = (r < 64) ? (128 + w * 64 + r) : (w * 16 + (r - 64));
        float wv = 0.f;
        if (!isOut) {
            int hh = j / 3, g = j - hh * 3;
            const float* W = (g == 0) ? W_i : (g == 1) ? W_o : W_c;
            wv = W[k * HH + h0 + hh];
        } else if ((oc0 + j) < OO && k >= II) {
            wv = W_out[(k - II) * OO + oc0 + j];
        }
        wsm[idx] = dup2(wv);
    }
    float rbi = 0.f, rbo = 0.f, rbc = 0.f;
    if (!isOut) {
        if (tid < 4) {
            float dv = 0.5f * sigm(d_values[h0 + tid]);
            float v = 1.f;
            for (int i = 0; i < KK; ++i) {
                v = v * ((float)i - dv) / ((float)i + 1.f);
                wd_sm[tid * KK + (KK - 1 - i)] = v;
            }
        }
        rbi = b_i[h0 + eh]; rbo = b_o[h0 + eh]; rbc = b_c[h0 + eh];
    }
    // Transpose inputs once: g_xT[t][k][b]
    for (int idx = gtid; idx < TSTEPS * II * BB; idx += GT) {
        int t = idx >> 13;
        int r = idx & 8191;
        int k = r & 127, b = r >> 7;
        g_xT[(size_t)t * 8192 + k * 64 + b] = inputs[((size_t)t * BB + b) * II + k];
    }
    for (int idx = gtid; idx < HH * BB; idx += GT) g_zH[idx] = 0.f;
    for (int idx = gtid; idx < KK * HH * BB; idx += GT) g_ring[idx] = 0.f;
    __syncthreads();
    gridbar(0);

    // Prefetch x(0) (gate blocks only)
    if (!isOut && tid == 0) {
        mbar_expect(xbar, 32768);
        bulk_g2s(smem_u32(xsm), g_xT, 32768, xbar);
    }

    unsigned hph = 0, xph = 0;
    unsigned barid = 1;

    // ---------------- main scan ----------------
    for (int u = 0; u <= TSTEPS; ++u) {
        const bool active = isOut ? (u >= 1) : (u < TSTEPS);

        if (active && tid == 0) {
            #pragma unroll
            for (int c = 0; c < 4; ++c) {
                mbar_expect(hbar0 + c * 8, 32768);
                bulk_g2s(smem_u32(hsm) + c * 32768, g_zH + c * 8192, 32768, hbar0 + c * 8);
            }
        }

        ull acc[12];
        if (active) {
            #pragma unroll
            for (int j = 0; j < 12; ++j) acc[j] = 0ULL;
            // x part first (gate blocks): prefetched last step.
            if (!isOut) {
                mbar_wait(xbar, xph);
                const float* zp = xsm + (wid * 16) * 64 + lane * 2;
                const ulonglong2* wp = (const ulonglong2*)(wsm + (size_t)(wid * 80 + 64) * 12);
                #pragma unroll 4
                for (int i = 0; i < 16; ++i) {
                    ull z = *(const ull*)(zp + i * 64);
                    ulonglong2 w0 = wp[i*6+0], w1 = wp[i*6+1], w2 = wp[i*6+2];
                    acc[0] = ffma2(z, w0.x, acc[0]);  acc[1] = ffma2(z, w0.y, acc[1]);
                    acc[2] = ffma2(z, w1.x, acc[2]);  acc[3] = ffma2(z, w1.y, acc[3]);
                    acc[4] = ffma2(z, w2.x, acc[4]);  acc[5] = ffma2(z, w2.y, acc[5]);
                    ulonglong2 w3 = wp[i*6+3], w4 = wp[i*6+4], w5 = wp[i*6+5];
                    acc[6] = ffma2(z, w3.x, acc[6]);   acc[7]  = ffma2(z, w3.y, acc[7]);
                    acc[8] = ffma2(z, w4.x, acc[8]);   acc[9]  = ffma2(z, w4.y, acc[9]);
                    acc[10] = ffma2(z, w5.x, acc[10]); acc[11] = ffma2(z, w5.y, acc[11]);
                }
            }
            // h part: wait only this warp-pair's chunk.
            mbar_wait(hbar0 + (wid >> 1) * 8, hph);
            const float* zp = hsm + (wid * 64) * 64 + lane * 2;
            const ulonglong2* wp = (const ulonglong2*)(wsm + (size_t)(wid * 80) * 12);
            #pragma unroll 4
            for (int i = 0; i < 64; ++i) {
                ull z = *(const ull*)(zp + i * 64);
                ulonglong2 w0 = wp[i*6+0], w1 = wp[i*6+1], w2 = wp[i*6+2];
                acc[0] = ffma2(z, w0.x, acc[0]);  acc[1] = ffma2(z, w0.y, acc[1]);
                acc[2] = ffma2(z, w1.x, acc[2]);  acc[3] = ffma2(z, w1.y, acc[3]);
                acc[4] = ffma2(z, w2.x, acc[4]);  acc[5] = ffma2(z, w2.y, acc[5]);
                ulonglong2 w3 = wp[i*6+3], w4 = wp[i*6+4], w5 = wp[i*6+5];
                acc[6] = ffma2(z, w3.x, acc[6]);   acc[7]  = ffma2(z, w3.y, acc[7]);
                acc[8] = ffma2(z, w4.x, acc[8]);   acc[9]  = ffma2(z, w4.y, acc[9]);
                acc[10] = ffma2(z, w5.x, acc[10]); acc[11] = ffma2(z, w5.y, acc[11]);
            }
        }
        __syncthreads();   // GEMM reads of hsm/xsm done before redsm / x-prefetch

        // Prefetch x(u+1) (gate blocks) — overlaps reduce/elementwise/barrier.
        if (!isOut && (u + 1) < TSTEPS && tid == 0) {
            mbar_expect(xbar, 32768);
            bulk_g2s(smem_u32(xsm), g_xT + (size_t)(u + 1) * 8192, 32768, xbar);
        }

        if (active) {
            #pragma unroll
            for (int j = 0; j < 12; ++j)
                redsm[(wid * 12 + j) * 32 + lane] = acc[j];
        }
        __syncthreads();

        if (active) {
            if (isOut) {
                // outputs for step u-1; thread covers 3 (col,b) cells
                #pragma unroll
                for (int q = 0; q < 3; ++q) {
                    int cix = tid + q * 256;
                    int j = cix >> 6, b = cix & 63;
                    int oc = oc0 + j;
                    if (oc < OO) {
                        float s = 0.f;
                        #pragma unroll
                        for (int w = 0; w < 8; ++w)
                            s += redf[((w * 12 + j) * 32 + (b >> 1)) * 2 + (b & 1)];
                        out[((size_t)(u - 1) * BB + b) * OO + oc] = s + b_out[oc];
                    }
                }
            } else {
                // fused reduce + elementwise for (h0+eh, eb)
                float pi = rbi, po = rbo, pc = rbc;
                int bhalf = (eb >> 1) * 2 + (eb & 1);
                #pragma unroll
                for (int w = 0; w < 8; ++w) {
                    int base = ((w * 12 + eh * 3) * 32) * 2 + bhalf;
                    pi += redf[base];
                    po += redf[base + 64];
                    pc += redf[base + 128];
                }
                float iv = sigm(pi);
                float ov = sigm(po);
                float gv = tanhf(pc);
                int h = h0 + eh;
                float l0 = 0.f, l1 = 0.f, l2 = 0.f, l3 = 0.f;
                #pragma unroll
                for (int j = 0; j < KK; j += 4) {
                    int s0 = (u + j    ) & 31;
                    int s1 = (u + j + 1) & 31;
                    int s2 = (u + j + 2) & 31;
                    int s3 = (u + j + 3) & 31;
                    l0 += wd_sm[eh * KK + j    ] * g_ring[(s0 << 15) + h * 64 + eb];
                    l1 += wd_sm[eh * KK + j + 1] * g_ring[(s1 << 15) + h * 64 + eb];
                    l2 += wd_sm[eh * KK + j + 2] * g_ring[(s2 << 15) + h * 64 + eb];
                    l3 += wd_sm[eh * KK + j + 3] * g_ring[(s3 << 15) + h * 64 + eb];
                }
                float cc = iv * gv - ((l0 + l1) + (l2 + l3));
                float hn = ov * tanhf(cc);
                g_ring[((u & 31) << 15) + h * 64 + eb] = cc;
                g_zH[h * 64 + eb] = hn;
                if (u == TSTEPS - 1)
                    out[(size_t)TSTEPS * BB * OO + (size_t)eb * HH + h] = hn;
            }
            hph ^= 1;
            if (!isOut) xph ^= 1;
        }
        gridbar(barid++);
    }

    // hc_last[j][b][h]: slot j holds c_{480+j}
    const size_t OFF_HC = (size_t)TSTEPS * BB * OO + (size_t)BB * HH;
    for (int idx = gtid; idx < KK * BB * HH; idx += GT) {
        int j = idx >> 15;
        int r = idx & 32767;
        int b = r >> 9, h = r & 511;
        out[OFF_HC + idx] = __ldcg(&g_ring[((size_t)j << 15) + h * 64 + b]);
    }
}

extern "C" void kernel_launch(void* const* d_in, const int* in_sizes, int n_in,
                              void* d_out, int out_size) {
    (void)in_sizes; (void)n_in; (void)out_size;
    const float* inputs   = (const float*)d_in[0];
    const float* W_i      = (const float*)d_in[1];
    const float* b_i      = (const float*)d_in[2];
    const float* W_o      = (const float*)d_in[3];
    const float* b_o      = (const float*)d_in[4];
    const float* W_c      = (const float*)d_in[5];
    const float* b_c      = (const float*)d_in[6];
    const float* W_out    = (const float*)d_in[7];
    const float* b_out    = (const float*)d_in[8];
    const float* d_values = (const float*)d_in[9];
    float* out = (float*)d_out;

    cudaFuncSetAttribute(mlstm_kernel, cudaFuncAttributeMaxDynamicSharedMemorySize, SMEM_BYTES);
    mlstm_kernel<<<NBLK, NTH, SMEM_BYTES>>>(inputs, W_i, b_i, W_o, b_o, W_c, b_c,
                                            W_out, b_out, d_values, out);
}